// round 17
// baseline (speedup 1.0000x reference)
#include <cuda_runtime.h>
#include <cuda_bf16.h>
#include <math.h>
#include <cstdint>

// Problem constants
#define CIN   256
#define COUT  512
#define HWSZ  3136
#define BATCH 32
#define NTOT  (BATCH*HWSZ)   // 100352
#define NGRP  32
#define CPG   (COUT/NGRP)
#define GELEMS (CPG*HWSZ)
#define EPS_GN 1e-5f
#define HT_MIN -2.0f
#define HT_MAX  2.0f

// Device-global scratch
__device__ float g_sum [BATCH*NGRP];
__device__ float g_ssum[BATCH*NGRP];
__device__ float g_mean[BATCH*NGRP];
__device__ float g_rstd[BATCH*NGRP];
__device__ __align__(16) __nv_bfloat16 g_w_hi[COUT*CIN];   // [o][c]
__device__ __align__(16) __nv_bfloat16 g_w_lo[COUT*CIN];

// ---------------- warp-level MMA helpers (sm_80+ baseline ISA) ----------------
__device__ __forceinline__ uint32_t smem_u32(const void* p) {
    uint32_t a;
    asm("{ .reg .u64 t; cvta.to.shared.u64 t, %1; cvt.u32.u64 %0, t; }" : "=r"(a) : "l"(p));
    return a;
}
__device__ __forceinline__ void ldsm_x4(uint32_t* r, uint32_t addr) {
    asm volatile("ldmatrix.sync.aligned.m8n8.x4.shared.b16 {%0,%1,%2,%3}, [%4];"
        : "=r"(r[0]), "=r"(r[1]), "=r"(r[2]), "=r"(r[3]) : "r"(addr));
}
__device__ __forceinline__ void ldsm_x4_t(uint32_t* r, uint32_t addr) {
    asm volatile("ldmatrix.sync.aligned.m8n8.x4.trans.shared.b16 {%0,%1,%2,%3}, [%4];"
        : "=r"(r[0]), "=r"(r[1]), "=r"(r[2]), "=r"(r[3]) : "r"(addr));
}
__device__ __forceinline__ void mma_bf16(float* d, const uint32_t* a, const uint32_t* b) {
    asm volatile("mma.sync.aligned.m16n8k16.row.col.f32.bf16.bf16.f32 "
        "{%0,%1,%2,%3}, {%4,%5,%6,%7}, {%8,%9}, {%0,%1,%2,%3};"
        : "+f"(d[0]), "+f"(d[1]), "+f"(d[2]), "+f"(d[3])
        : "r"(a[0]), "r"(a[1]), "r"(a[2]), "r"(a[3]), "r"(b[0]), "r"(b[1]));
}

// pack 2 floats -> bf16x2 hi and lo words
__device__ __forceinline__ void split2(float f0, float f1, uint32_t& hi, uint32_t& lo) {
    __nv_bfloat16 h0 = __float2bfloat16(f0);
    __nv_bfloat16 h1 = __float2bfloat16(f1);
    __nv_bfloat16 l0 = __float2bfloat16(f0 - __bfloat162float(h0));
    __nv_bfloat16 l1 = __float2bfloat16(f1 - __bfloat162float(h1));
    __nv_bfloat162 hp = __halves2bfloat162(h0, h1);
    __nv_bfloat162 lp = __halves2bfloat162(l0, l1);
    hi = *(uint32_t*)&hp;
    lo = *(uint32_t*)&lp;
}
__device__ __forceinline__ void split8(const float4 v0, const float4 v1,
                                       uint4& hi, uint4& lo) {
    split2(v0.x, v0.y, hi.x, lo.x);
    split2(v0.z, v0.w, hi.y, lo.y);
    split2(v1.x, v1.y, hi.z, lo.z);
    split2(v1.z, v1.w, hi.w, lo.w);
}

// ---------------------------------------------------------------------------
// Small prep kernels
// ---------------------------------------------------------------------------
__global__ void convert_w_kernel(const float* __restrict__ W) {
    int i = blockIdx.x * 256 + threadIdx.x;       // COUT*CIN = 131072
    float v = W[i];
    __nv_bfloat16 hi = __float2bfloat16(v);
    g_w_hi[i] = hi;
    g_w_lo[i] = __float2bfloat16(v - __bfloat162float(hi));
}
__global__ void zero_stats_kernel() {
    int i = blockIdx.x * 256 + threadIdx.x;       // 2048 covers both arrays
    if (i < BATCH * NGRP) { g_sum[i] = 0.0f; g_ssum[i] = 0.0f; }
    else { int j = i - BATCH * NGRP; g_ssum[j] = 0.0f; g_sum[j] = 0.0f; }
}
__global__ void finalize_stats_kernel() {
    int bg = blockIdx.x * 256 + threadIdx.x;
    if (bg < BATCH * NGRP) {
        const float inv_n = 1.0f / (float)GELEMS;
        float mean = g_sum[bg] * inv_n;
        float var  = g_ssum[bg] * inv_n - mean * mean;
        g_mean[bg] = mean;
        g_rstd[bg] = rsqrtf(var + EPS_GN);
    }
}

// ---------------------------------------------------------------------------
// Tensor-core GEMM + fused GroupNorm partial stats.
// CTA: 128(cout) x 128(spatial) x BK=32. 8 warps = 4(m) x 2(n).
// B read directly from fp32 x (native layout), hi/lo split at STS.
// Double-buffered dynamic smem -> single __syncthreads per k-block.
// Epilogue: y store + per-warp (2 groups, 1 batch) s/ss shfl-reduce -> atomics.
// ---------------------------------------------------------------------------
#define PA 40    // A smem pitch (halves): 80B rows -> conflict-free ldmatrix
#define PB 136   // B smem pitch (halves): 272B rows -> conflict-free ldmatrix
#define SA_ELE (2*128*PA)            // per-buffer A halves (both precisions) = 10240
#define SB_ELE (2*32*PB)             // per-buffer B halves = 8704
#define BUF_ELE (SA_ELE + SB_ELE)    // 18944
#define SMEM_BYTES (2*BUF_ELE*2)     // 75776 B

__global__ __launch_bounds__(256, 1)
void gemm_mma_kernel(const float* __restrict__ x, float* __restrict__ y)
{
    extern __shared__ __align__(16) __nv_bfloat16 dsm[];
    // layout: [buf][ A: prec*128*PA | B: prec*32*PB ]
    const int tid  = threadIdx.x;
    const int lane = tid & 31;
    const int w    = tid >> 5;
    const int wm   = (w & 3) * 32;          // warp m offset (cout)
    const int wn   = (w >> 2) * 64;         // warp n offset (spatial)
    const int o0   = blockIdx.x * 128;      // cout tile
    const int n0   = blockIdx.y * 128;      // spatial tile

    #define sAp(buf, prec, row) (dsm + (buf)*BUF_ELE + (prec)*(128*PA) + (row)*PA)
    #define sBp(buf, prec, row) (dsm + (buf)*BUF_ELE + SA_ELE + (prec)*(32*PB) + (row)*PB)

    // B load coords: each 8-elem chunk stays within one batch (HWSZ%8==0)
    const int bn   = n0 + (tid & 15) * 8;
    const int bbB  = bn / HWSZ;
    const int hwB  = bn - bbB * HWSZ;
    const float* xbase = x + (size_t)bbB * CIN * HWSZ + hwB;   // + c*HWSZ

    float acc[2][8][4];
    #pragma unroll
    for (int i = 0; i < 2; i++)
        #pragma unroll
        for (int j = 0; j < 8; j++)
            #pragma unroll
            for (int q = 0; q < 4; q++) acc[i][j][q] = 0.0f;

    // ---- prologue: k-block 0 -> buffer 0 ----
    #pragma unroll
    for (int q = 0; q < 2; q++) {
        int i = tid + q * 256;
        int row = i >> 2, c16 = i & 3;
        size_t ge = (size_t)(o0 + row) * CIN + c16 * 8;
        *(uint4*)(sAp(0, 0, row) + c16 * 8) = *(const uint4*)(g_w_hi + ge);
        *(uint4*)(sAp(0, 1, row) + c16 * 8) = *(const uint4*)(g_w_lo + ge);
    }
    #pragma unroll
    for (int q = 0; q < 2; q++) {
        int i = tid + q * 256;
        int row = i >> 4, c16 = i & 15;
        const float* xp = xbase + (size_t)row * HWSZ;
        float4 v0 = *(const float4*)(xp);
        float4 v1 = *(const float4*)(xp + 4);
        uint4 hi, lo;
        split8(v0, v1, hi, lo);
        *(uint4*)(sBp(0, 0, row) + c16 * 8) = hi;
        *(uint4*)(sBp(0, 1, row) + c16 * 8) = lo;
    }
    __syncthreads();

    for (int kb = 0; kb < CIN / 32; kb++) {
        const int  cur  = kb & 1;
        const bool more = (kb + 1) < (CIN / 32);
        uint4 rAh[2], rAl[2];
        float4 rBv[2][2];
        if (more) {
            #pragma unroll
            for (int q = 0; q < 2; q++) {
                int i = tid + q * 256;
                int row = i >> 2, c16 = i & 3;
                size_t ge = (size_t)(o0 + row) * CIN + (kb + 1) * 32 + c16 * 8;
                rAh[q] = *(const uint4*)(g_w_hi + ge);
                rAl[q] = *(const uint4*)(g_w_lo + ge);
            }
            #pragma unroll
            for (int q = 0; q < 2; q++) {
                int i = tid + q * 256;
                int row = i >> 4;
                const float* xp = xbase + (size_t)((kb + 1) * 32 + row) * HWSZ;
                rBv[q][0] = *(const float4*)(xp);
                rBv[q][1] = *(const float4*)(xp + 4);
            }
        }

        #pragma unroll
        for (int ks = 0; ks < 2; ks++) {          // two k16 steps per block
            uint32_t ah[2][4], al[2][4];
            #pragma unroll
            for (int mi = 0; mi < 2; mi++) {
                const int r = wm + mi * 16 + (lane & 15);
                const int c = ks * 16 + (lane >> 4) * 8;
                ldsm_x4(ah[mi], smem_u32(sAp(cur, 0, r) + c));
                ldsm_x4(al[mi], smem_u32(sAp(cur, 1, r) + c));
            }
            uint32_t bh[4][4], bl[4][4];
            #pragma unroll
            for (int nj = 0; nj < 4; nj++) {
                const int r = ks * 16 + (lane & 15);
                const int c = wn + nj * 16 + (lane >> 4) * 8;
                ldsm_x4_t(bh[nj], smem_u32(sBp(cur, 0, r) + c));
                ldsm_x4_t(bl[nj], smem_u32(sBp(cur, 1, r) + c));
            }
            #pragma unroll
            for (int mi = 0; mi < 2; mi++)
                #pragma unroll
                for (int nj = 0; nj < 4; nj++)
                    #pragma unroll
                    for (int h = 0; h < 2; h++) {
                        float* d = acc[mi][nj * 2 + h];
                        mma_bf16(d, ah[mi], bh[nj] + h * 2);   // hi*hi
                        mma_bf16(d, ah[mi], bl[nj] + h * 2);   // hi*lo
                        mma_bf16(d, al[mi], bh[nj] + h * 2);   // lo*hi
                    }
        }

        if (more) {
            const int nxt = cur ^ 1;               // idle buffer: no sync needed
            #pragma unroll
            for (int q = 0; q < 2; q++) {
                int i = tid + q * 256;
                int row = i >> 2, c16 = i & 3;
                *(uint4*)(sAp(nxt, 0, row) + c16 * 8) = rAh[q];
                *(uint4*)(sAp(nxt, 1, row) + c16 * 8) = rAl[q];
            }
            #pragma unroll
            for (int q = 0; q < 2; q++) {
                int i = tid + q * 256;
                int row = i >> 4, c16 = i & 15;
                uint4 hi, lo;
                split8(rBv[q][0], rBv[q][1], hi, lo);
                *(uint4*)(sBp(nxt, 0, row) + c16 * 8) = hi;
                *(uint4*)(sBp(nxt, 1, row) + c16 * 8) = lo;
            }
            __syncthreads();   // single barrier per k-block: cur fully read, nxt ready
        }
    }

    // ---- epilogue: y store (warp n-span 64 within one batch, HWSZ%64==0) ----
    const int ng = n0 + wn;
    const int bb = ng / HWSZ;
    const int hwb = ng - bb * HWSZ + (lane & 3) * 2;
    const int rg = o0 + wm + (lane >> 2);
    #pragma unroll
    for (int mi = 0; mi < 2; mi++) {
        #pragma unroll
        for (int nf = 0; nf < 8; nf++) {
            const int hw = hwb + nf * 8;
            const float* d = acc[mi][nf];
            float* y0 = y + ((size_t)bb * COUT + rg + mi * 16) * HWSZ + hw;
            *(float2*)y0               = make_float2(d[0], d[1]);
            *(float2*)(y0 + 8 * HWSZ)  = make_float2(d[2], d[3]);
        }
    }

    // ---- fused GroupNorm partial stats ----
    // rows [wm, wm+15] are one group, [wm+16, wm+31] the next; one batch per warp.
    #pragma unroll
    for (int mi = 0; mi < 2; mi++) {
        float s = 0.0f, ss = 0.0f;
        #pragma unroll
        for (int nf = 0; nf < 8; nf++) {
            const float* d = acc[mi][nf];
            s  += (d[0] + d[1]) + (d[2] + d[3]);
            ss += (d[0] * d[0] + d[1] * d[1]) + (d[2] * d[2] + d[3] * d[3]);
        }
        #pragma unroll
        for (int o = 16; o > 0; o >>= 1) {
            s  += __shfl_down_sync(0xffffffffu, s, o);
            ss += __shfl_down_sync(0xffffffffu, ss, o);
        }
        if (lane == 0) {
            const int bg = bb * NGRP + ((o0 + wm + mi * 16) >> 4);
            atomicAdd(&g_sum[bg],  s);
            atomicAdd(&g_ssum[bg], ss);
        }
    }
}

// ---------------------------------------------------------------------------
// normalize + affine + hardtanh, in place, float4.
// ---------------------------------------------------------------------------
__global__ __launch_bounds__(256)
void norm_kernel(float* __restrict__ y,
                 const float* __restrict__ gamma,
                 const float* __restrict__ beta)
{
    const size_t i4  = (size_t)blockIdx.x * 256 + threadIdx.x;
    const size_t idx = i4 * 4;
    const int o  = (int)((idx / HWSZ) % COUT);
    const int bg = (int)(idx / GELEMS);
    const float r  = g_rstd[bg];
    const float ga = gamma[o] * r;
    const float be = beta[o] - g_mean[bg] * ga;
    float4 v = *(float4*)(y + idx);
    v.x = fminf(fmaxf(fmaf(v.x, ga, be), HT_MIN), HT_MAX);
    v.y = fminf(fmaxf(fmaf(v.y, ga, be), HT_MIN), HT_MAX);
    v.z = fminf(fmaxf(fmaf(v.z, ga, be), HT_MIN), HT_MAX);
    v.w = fminf(fmaxf(fmaf(v.w, ga, be), HT_MIN), HT_MAX);
    *(float4*)(y + idx) = v;
}

// ---------------------------------------------------------------------------
extern "C" void kernel_launch(void* const* d_in, const int* in_sizes, int n_in,
                              void* d_out, int out_size)
{
    const float* x     = (const float*)d_in[0];
    const float* W     = (const float*)d_in[1];
    const float* gamma = (const float*)d_in[2];
    const float* beta  = (const float*)d_in[3];
    float* y = (float*)d_out;

    cudaFuncSetAttribute(gemm_mma_kernel,
                         cudaFuncAttributeMaxDynamicSharedMemorySize, SMEM_BYTES);

    convert_w_kernel<<<COUT * CIN / 256, 256>>>(W);
    zero_stats_kernel<<<4, 256>>>();
    gemm_mma_kernel<<<dim3(COUT / 128, NTOT / 128), 256, SMEM_BYTES>>>(x, y);
    finalize_stats_kernel<<<4, 256>>>();
    const size_t total4 = (size_t)BATCH * COUT * HWSZ / 4;
    norm_kernel<<<(unsigned)(total4 / 256), 256>>>(y, gamma, beta);
}